// round 5
// baseline (speedup 1.0000x reference)
#include <cuda_runtime.h>
#include <math.h>

#define NIMG 8
#define HH 224
#define WW 224
#define HW (HH * WW)          // 50176
#define KC 100
#define NITER 10
#define TPB 1024
#define BPI (HW / TPB)        // 49 blocks per image, exact

// ratio = float(10.0 / sqrt(224*224/100.0)) = float(10/22.4)
#define RATIO 0.44642857142857145f

// Persistent device state (no allocations allowed in kernel_launch)
__device__ float4 g_cA[NIMG * KC];      // (fy, fx, r, g)
__device__ float2 g_cB[NIMG * KC];      // (b, csq)
__device__ float  g_acc[NIMG * KC * 6]; // per-center: sum fy,fx,r,g,b + count

__constant__ int c_grid[10] = {11, 33, 56, 78, 100, 123, 145, 168, 190, 212};

// non-contracted helpers (match XLA's separate mul + add for sum(x*x))
__device__ __forceinline__ float sq5(float a, float b, float c, float d, float e) {
    float s = __fadd_rn(__fmul_rn(a, a), __fmul_rn(b, b));
    s = __fadd_rn(s, __fmul_rn(c, c));
    s = __fadd_rn(s, __fmul_rn(d, d));
    s = __fadd_rn(s, __fmul_rn(e, e));
    return s;
}

// ---------------------------------------------------------------------------
// Init: centers from regular grid pixels, zero accumulators
// ---------------------------------------------------------------------------
__global__ void slic_init(const float* __restrict__ img) {
    int b = blockIdx.x;
    int t = threadIdx.x;
    for (int i = t; i < KC * 6; i += blockDim.x)
        g_acc[b * KC * 6 + i] = 0.0f;
    if (t < KC) {
        int iy = t / 10, ix = t % 10;
        int cy = c_grid[iy], cx = c_grid[ix];
        const float* p = img + (b * HW + cy * WW + cx) * 3;
        float r = p[0], g = p[1], bl = p[2];
        float fy = __fmul_rn((float)cy, RATIO);
        float fx = __fmul_rn((float)cx, RATIO);
        float csq = sq5(fy, fx, r, g, bl);
        g_cA[b * KC + t] = make_float4(fy, fx, r, g);
        g_cB[b * KC + t] = make_float2(bl, csq);
    }
}

// ---------------------------------------------------------------------------
// Assign (+accumulate, or final output)
// grid = (BPI, NIMG), block = 1024
// ---------------------------------------------------------------------------
template <bool FINAL>
__global__ void __launch_bounds__(TPB)
slic_assign(const float* __restrict__ img,
            float* __restrict__ labels_out,   // float32 output! (harness dtype)
            float* __restrict__ mean_out) {
    __shared__ float4 sA[KC];
    __shared__ float2 sB[KC];
    __shared__ float  sac[KC * 6];

    const int b = blockIdx.y;
    const int t = threadIdx.x;

    if (t < KC) {
        sA[t] = g_cA[b * KC + t];
        sB[t] = g_cB[b * KC + t];
    }
    if (!FINAL) {
        for (int i = t; i < KC * 6; i += TPB) sac[i] = 0.0f;
    }
    __syncthreads();

    const int pix = blockIdx.x * TPB + t;       // < HW exactly
    const int y = pix / WW;
    const int x = pix - y * WW;

    const float* p = img + (b * HW + pix) * 3;
    const float r  = p[0];
    const float g  = p[1];
    const float bl = p[2];
    const float fy = __fmul_rn((float)y, RATIO);
    const float fx = __fmul_rn((float)x, RATIO);
    const float fsq = sq5(fy, fx, r, g, bl);

    float bd = 3.4e38f;
    int   bk = 0;

#pragma unroll 5
    for (int k = 0; k < KC; ++k) {
        float4 a = sA[k];
        float2 c = sB[k];
        float t0 = __fmul_rn(fy, a.x);
        t0 = fmaf(fx, a.y, t0);
        t0 = fmaf(r,  a.z, t0);
        t0 = fmaf(g,  a.w, t0);
        t0 = fmaf(bl, c.x, t0);
        // d = (fsq + csq) - 2*t0 ; fma(-2,t0,base) is bit-identical (x2 exact)
        float d = fmaf(-2.0f, t0, __fadd_rn(fsq, c.y));
        if (d < bd) { bd = d; bk = k; }   // strict < == first-min tie-break
    }

    if (FINAL) {
        labels_out[b * HW + pix] = (float)bk;   // label as float VALUE
        float4 a = sA[bk];
        float2 c = sB[bk];
        float* mo = mean_out + (b * HW + pix) * 3;
        mo[0] = a.z;
        mo[1] = a.w;
        mo[2] = c.x;
    } else {
        float* s = sac + bk * 6;
        atomicAdd(s + 0, fy);
        atomicAdd(s + 1, fx);
        atomicAdd(s + 2, r);
        atomicAdd(s + 3, g);
        atomicAdd(s + 4, bl);
        atomicAdd(s + 5, 1.0f);
        __syncthreads();
        for (int i = t; i < KC * 6; i += TPB) {
            float v = sac[i];
            if (v != 0.0f) atomicAdd(&g_acc[b * KC * 6 + i], v);
        }
    }
}

// ---------------------------------------------------------------------------
// Update centers: mean of assigned pixels (keep old if empty), re-zero acc
// ---------------------------------------------------------------------------
__global__ void slic_update() {
    int b = blockIdx.x;
    int k = threadIdx.x;
    if (k < KC) {
        float* a = &g_acc[(b * KC + k) * 6];
        float s0 = a[0], s1 = a[1], s2 = a[2], s3 = a[3], s4 = a[4];
        float cnt = a[5];
        float4 oa = g_cA[b * KC + k];
        float2 ob = g_cB[b * KC + k];
        float den = fmaxf(cnt, 1.0f);
        float ny, nx, nr, ng, nb;
        if (cnt > 0.0f) {
            ny = __fdiv_rn(s0, den);
            nx = __fdiv_rn(s1, den);
            nr = __fdiv_rn(s2, den);
            ng = __fdiv_rn(s3, den);
            nb = __fdiv_rn(s4, den);
        } else {
            ny = oa.x; nx = oa.y; nr = oa.z; ng = oa.w; nb = ob.x;
        }
        float csq = sq5(ny, nx, nr, ng, nb);
        g_cA[b * KC + k] = make_float4(ny, nx, nr, ng);
        g_cB[b * KC + k] = make_float2(nb, csq);
        // re-zero for next iteration
        a[0] = 0.0f; a[1] = 0.0f; a[2] = 0.0f;
        a[3] = 0.0f; a[4] = 0.0f; a[5] = 0.0f;
    }
}

// ---------------------------------------------------------------------------
// Launch: init -> 10 x (assign+acc, update) -> final assign (labels + mean)
// d_out layout, ALL float32 (__output__ dtype):
//   [0, NIMG*HW)            labels as float values (0.0 .. 99.0)
//   [NIMG*HW, NIMG*HW*4)    mean image (NIMG,H,W,3)
// ---------------------------------------------------------------------------
extern "C" void kernel_launch(void* const* d_in, const int* in_sizes, int n_in,
                              void* d_out, int out_size) {
    const float* img = (const float*)d_in[0];
    float* labels = (float*)d_out;
    float* meanim = (float*)d_out + (size_t)NIMG * HW;

    slic_init<<<NIMG, 128>>>(img);

    dim3 grid(BPI, NIMG);
    for (int it = 0; it < NITER; ++it) {
        slic_assign<false><<<grid, TPB>>>(img, nullptr, nullptr);
        slic_update<<<NIMG, 128>>>();
    }
    slic_assign<true><<<grid, TPB>>>(img, labels, meanim);
}

// round 6
// speedup vs baseline: 1.9000x; 1.9000x over previous
#include <cuda_runtime.h>
#include <math.h>

#define NIMG 8
#define HH 224
#define WW 224
#define HW (HH * WW)          // 50176
#define KC 100
#define NITER 10
#define TPB 256
#define PPT 4                  // pixels per thread
#define PXB (TPB * PPT)        // 1024 pixels per block
#define BPI (HW / PXB)         // 49 blocks per image, exact
#define NREP 4                 // replicated shared accumulators

// ratio = float(10.0 / sqrt(224*224/100.0)) = float(10/22.4)
#define RATIO 0.44642857142857145f

// Persistent device state (no allocations allowed in kernel_launch)
__device__ float4 g_cA[NIMG * KC];      // (fy, fx, r, g)
__device__ float2 g_cB[NIMG * KC];      // (b, csq)
__device__ float  g_acc[NIMG * KC * 6]; // per-center: sum fy,fx,r,g,b + count

__constant__ int c_grid[10] = {11, 33, 56, 78, 100, 123, 145, 168, 190, 212};

// non-contracted (match XLA's separate mul + add for sum(x*x))
__device__ __forceinline__ float sq5(float a, float b, float c, float d, float e) {
    float s = __fadd_rn(__fmul_rn(a, a), __fmul_rn(b, b));
    s = __fadd_rn(s, __fmul_rn(c, c));
    s = __fadd_rn(s, __fmul_rn(d, d));
    s = __fadd_rn(s, __fmul_rn(e, e));
    return s;
}

// ---------------------------------------------------------------------------
__global__ void slic_init(const float* __restrict__ img) {
    int b = blockIdx.x;
    int t = threadIdx.x;
    for (int i = t; i < KC * 6; i += blockDim.x)
        g_acc[b * KC * 6 + i] = 0.0f;
    if (t < KC) {
        int iy = t / 10, ix = t % 10;
        int cy = c_grid[iy], cx = c_grid[ix];
        const float* p = img + (b * HW + cy * WW + cx) * 3;
        float r = p[0], g = p[1], bl = p[2];
        float fy = __fmul_rn((float)cy, RATIO);
        float fx = __fmul_rn((float)cx, RATIO);
        float csq = sq5(fy, fx, r, g, bl);
        g_cA[b * KC + t] = make_float4(fy, fx, r, g);
        g_cB[b * KC + t] = make_float2(bl, csq);
    }
}

// ---------------------------------------------------------------------------
// Assign (+accumulate, or final output).  grid=(BPI,NIMG), block=TPB, 4 px/thread.
// ---------------------------------------------------------------------------
template <bool FINAL>
__global__ void __launch_bounds__(TPB)
slic_assign(const float* __restrict__ img,
            float* __restrict__ labels_out,   // labels as float32 values
            float* __restrict__ mean_out) {
    __shared__ float4 sA[KC];
    __shared__ float2 sB[KC];
    __shared__ float  sac[NREP][KC * 6];

    const int b = blockIdx.y;
    const int t = threadIdx.x;

    if (t < KC) {
        sA[t] = g_cA[b * KC + t];
        sB[t] = g_cB[b * KC + t];
    }
    if (!FINAL) {
        for (int i = t; i < NREP * KC * 6; i += TPB)
            ((float*)sac)[i] = 0.0f;
    }
    __syncthreads();

    const int pix0 = blockIdx.x * PXB + t * PPT;   // 4 consecutive pixels

    // load 4 pixels = 12 floats = 3 x float4 (16B aligned: pix0*3*4 % 16 == 0)
    const float4* p4 = (const float4*)(img + ((size_t)b * HW + pix0) * 3);
    float4 q0 = p4[0], q1 = p4[1], q2 = p4[2];

    float rv[PPT]  = {q0.x, q0.w, q1.z, q2.y};
    float gv[PPT]  = {q0.y, q1.x, q1.w, q2.z};
    float bv[PPT]  = {q0.z, q1.y, q2.x, q2.w};

    float fyv[PPT], fxv[PPT], fsqv[PPT], bd[PPT];
    int   bk[PPT];

#pragma unroll
    for (int i = 0; i < PPT; ++i) {
        int pix = pix0 + i;
        int y = pix / WW;
        int x = pix - y * WW;
        fyv[i] = __fmul_rn((float)y, RATIO);
        fxv[i] = __fmul_rn((float)x, RATIO);
        fsqv[i] = sq5(fyv[i], fxv[i], rv[i], gv[i], bv[i]);
        bd[i] = 3.4e38f;
        bk[i] = 0;
    }

#pragma unroll 4
    for (int k = 0; k < KC; ++k) {
        float4 a = sA[k];
        float2 c = sB[k];
#pragma unroll
        for (int i = 0; i < PPT; ++i) {
            float t0 = __fmul_rn(fyv[i], a.x);
            t0 = fmaf(fxv[i], a.y, t0);
            t0 = fmaf(rv[i],  a.z, t0);
            t0 = fmaf(gv[i],  a.w, t0);
            t0 = fmaf(bv[i],  c.x, t0);
            // d = (fsq + csq) - 2*t0 ; fma(-2,t0,base) bit-identical (x2 exact)
            float d = fmaf(-2.0f, t0, __fadd_rn(fsqv[i], c.y));
            bool lt = d < bd[i];              // strict < == first-min tie-break
            bd[i] = lt ? d : bd[i];
            bk[i] = lt ? k : bk[i];
        }
    }

    if (FINAL) {
#pragma unroll
        for (int i = 0; i < PPT; ++i) {
            int pix = pix0 + i;
            labels_out[(size_t)b * HW + pix] = (float)bk[i];
            float4 a = sA[bk[i]];
            float2 c = sB[bk[i]];
            float* mo = mean_out + ((size_t)b * HW + pix) * 3;
            mo[0] = a.z;
            mo[1] = a.w;
            mo[2] = c.x;
        }
    } else {
        // merge consecutive same-label pixels, flush runs to replicated shared acc
        float* rep = sac[t & (NREP - 1)];
        int   key = bk[0];
        float s0 = fyv[0], s1 = fxv[0], s2 = rv[0], s3 = gv[0], s4 = bv[0], s5 = 1.0f;
#pragma unroll
        for (int i = 1; i < PPT; ++i) {
            if (bk[i] == key) {
                s0 += fyv[i]; s1 += fxv[i]; s2 += rv[i];
                s3 += gv[i];  s4 += bv[i];  s5 += 1.0f;
            } else {
                float* s = rep + key * 6;
                atomicAdd(s + 0, s0); atomicAdd(s + 1, s1);
                atomicAdd(s + 2, s2); atomicAdd(s + 3, s3);
                atomicAdd(s + 4, s4); atomicAdd(s + 5, s5);
                key = bk[i];
                s0 = fyv[i]; s1 = fxv[i]; s2 = rv[i];
                s3 = gv[i];  s4 = bv[i];  s5 = 1.0f;
            }
        }
        {
            float* s = rep + key * 6;
            atomicAdd(s + 0, s0); atomicAdd(s + 1, s1);
            atomicAdd(s + 2, s2); atomicAdd(s + 3, s3);
            atomicAdd(s + 4, s4); atomicAdd(s + 5, s5);
        }
        __syncthreads();
        for (int i = t; i < KC * 6; i += TPB) {
            float v = sac[0][i] + sac[1][i] + sac[2][i] + sac[3][i];
            if (v != 0.0f) atomicAdd(&g_acc[b * KC * 6 + i], v);
        }
    }
}

// ---------------------------------------------------------------------------
__global__ void slic_update() {
    int b = blockIdx.x;
    int k = threadIdx.x;
    if (k < KC) {
        float* a = &g_acc[(b * KC + k) * 6];
        float s0 = a[0], s1 = a[1], s2 = a[2], s3 = a[3], s4 = a[4];
        float cnt = a[5];
        float4 oa = g_cA[b * KC + k];
        float2 ob = g_cB[b * KC + k];
        float den = fmaxf(cnt, 1.0f);
        float ny, nx, nr, ng, nb;
        if (cnt > 0.0f) {
            ny = __fdiv_rn(s0, den);
            nx = __fdiv_rn(s1, den);
            nr = __fdiv_rn(s2, den);
            ng = __fdiv_rn(s3, den);
            nb = __fdiv_rn(s4, den);
        } else {
            ny = oa.x; nx = oa.y; nr = oa.z; ng = oa.w; nb = ob.x;
        }
        float csq = sq5(ny, nx, nr, ng, nb);
        g_cA[b * KC + k] = make_float4(ny, nx, nr, ng);
        g_cB[b * KC + k] = make_float2(nb, csq);
        a[0] = 0.0f; a[1] = 0.0f; a[2] = 0.0f;
        a[3] = 0.0f; a[4] = 0.0f; a[5] = 0.0f;
    }
}

// ---------------------------------------------------------------------------
// d_out (all float32): [0, NIMG*HW) labels ; [NIMG*HW, NIMG*HW*4) mean image
// ---------------------------------------------------------------------------
extern "C" void kernel_launch(void* const* d_in, const int* in_sizes, int n_in,
                              void* d_out, int out_size) {
    const float* img = (const float*)d_in[0];
    float* labels = (float*)d_out;
    float* meanim = (float*)d_out + (size_t)NIMG * HW;

    slic_init<<<NIMG, 128>>>(img);

    dim3 grid(BPI, NIMG);
    for (int it = 0; it < NITER; ++it) {
        slic_assign<false><<<grid, TPB>>>(img, nullptr, nullptr);
        slic_update<<<NIMG, 128>>>();
    }
    slic_assign<true><<<grid, TPB>>>(img, labels, meanim);
}